// round 16
// baseline (speedup 1.0000x reference)
#include <cuda_runtime.h>
#include <math.h>

// ---------------- problem constants ----------------
#define Bc   16
#define Tc   1536
#define Vc   64
#define F1c  16
#define Hc   4
#define FOc  8
#define F2c  32
#define K1c  32
#define K3c  16
#define NG   16          // graphs per block (two pool-8 windows)
#define EMAX 512
#define NTHR 768
#define TP   192

#define XROW 48          // window NG-1+32 = 47, pad to 48
#define XS_F (Vc * XROW)
// h1 (16-ch) row stride
#define H16  20
#define HG16 (Vc * H16)     // 1280 floats per graph

// ---------------- device scratch ----------------
__device__ float d_wc[K1c * 16];   // [k][f]  bn-folded conv weights
__device__ float d_bc[16];         // bn shift per f
__device__ float d_A[64];          // [head][16]  W·a_src folded
__device__ float d_Dv[64];         // [head][16]  W·a_dst folded
__device__ float d_scale2[32], d_shift2[32], d_scale3[32], d_shift3[32];
__device__ int   d_off[Vc + 1];
__device__ int   d_srcs[EMAX];
__device__ int   d_roff[Vc + 1];
__device__ int   d_rdst[EMAX];
__device__ float d_pbuf[Bc * TP * F2c];   // pooled BN2+ELU output, (b,tc,f)

// ---------------- packed f32x2 helpers ----------------
typedef unsigned long long ull;
__device__ __forceinline__ ull pack2(float lo, float hi) {
    ull r;
    asm("mov.b64 %0, {%1, %2};" : "=l"(r) : "f"(lo), "f"(hi));
    return r;
}
__device__ __forceinline__ void fma2(ull& d, ull a, ull b) {
    asm("fma.rn.f32x2 %0, %1, %2, %0;" : "+l"(d) : "l"(a), "l"(b));
}
__device__ __forceinline__ void unpack2(ull v, float& lo, float& hi) {
    asm("mov.b64 {%0, %1}, %2;" : "=f"(lo), "=f"(hi) : "l"(v));
}

// ---------------- setup: 1024 threads, parallel degree sums ----------------
__global__ void setup_kernel(const float* __restrict__ conv1_w,
                             const float* __restrict__ bn1_g, const float* __restrict__ bn1_b,
                             const float* __restrict__ bn1_m, const float* __restrict__ bn1_v,
                             const float* __restrict__ gat_w,
                             const float* __restrict__ gat_asrc, const float* __restrict__ gat_adst,
                             const float* __restrict__ bn2_g, const float* __restrict__ bn2_b,
                             const float* __restrict__ bn2_m, const float* __restrict__ bn2_v,
                             const float* __restrict__ bn3_g, const float* __restrict__ bn3_b,
                             const float* __restrict__ bn3_m, const float* __restrict__ bn3_v,
                             const int* __restrict__ edge_index, int E) {
    __shared__ float sc1[F1c], sh1[F1c];
    __shared__ float s_gw[F1c * 32];
    __shared__ int sedge[2 * EMAX];
    __shared__ int cnt16[Vc][16], rcnt16[Vc][16];
    __shared__ int sdeg[Vc], rdeg[Vc];
    __shared__ int soff[Vc + 1], rsoff[Vc + 1];
    int tid = threadIdx.x;

    for (int i = tid; i < 2 * E; i += blockDim.x) sedge[i] = edge_index[i];
    for (int i = tid; i < F1c * 32; i += blockDim.x) s_gw[i] = gat_w[i];
    if (tid < F1c) {
        float s = bn1_g[tid] * rsqrtf(bn1_v[tid] + 1e-5f);
        sc1[tid] = s;
        sh1[tid] = bn1_b[tid] - bn1_m[tid] * s;
    }
    if (tid < F2c) {
        float s2 = bn2_g[tid] * rsqrtf(bn2_v[tid] + 1e-5f);
        d_scale2[tid] = s2; d_shift2[tid] = bn2_b[tid] - bn2_m[tid] * s2;
        float s3 = bn3_g[tid] * rsqrtf(bn3_v[tid] + 1e-5f);
        d_scale3[tid] = s3; d_shift3[tid] = bn3_b[tid] - bn3_m[tid] * s3;
    }
    __syncthreads();
    for (int i = tid; i < K1c * 16; i += blockDim.x) {
        int k = i >> 4, f = i & 15;
        d_wc[i] = sc1[f] * conv1_w[f * K1c + k];
    }
    if (tid < 16) d_bc[tid] = sh1[tid];
    if (tid < 64) {
        int head = tid >> 4, f = tid & 15;
        float sa = 0.f, sd = 0.f;
        #pragma unroll
        for (int fo = 0; fo < FOc; fo++) {
            float wv = s_gw[f * 32 + head * FOc + fo];
            sa = fmaf(wv, gat_asrc[head * FOc + fo], sa);
            sd = fmaf(wv, gat_adst[head * FOc + fo], sd);
        }
        d_A[head * 16 + f]  = sa;
        d_Dv[head * 16 + f] = sd;
    }
    // forward + reverse CSR (order-preserving, 16 threads/vertex)
    const int* src = sedge;
    const int* dst = sedge + E;
    const int qsz = (E + 15) >> 4;
    const int v = tid >> 4, q = tid & 15;
    const int lo = q * qsz;
    const int hi = min(E, lo + qsz);
    {
        int c = 0, rc = 0;
        for (int e = lo; e < hi; e++) { c += (dst[e] == v); rc += (src[e] == v); }
        cnt16[v][q] = c; rcnt16[v][q] = rc;
    }
    __syncthreads();
    if (tid < Vc) {
        int s = 0;
        #pragma unroll
        for (int qq = 0; qq < 16; qq++) s += cnt16[tid][qq];
        sdeg[tid] = s;
    } else if (tid < 2 * Vc) {
        int v2 = tid - Vc;
        int s = 0;
        #pragma unroll
        for (int qq = 0; qq < 16; qq++) s += rcnt16[v2][qq];
        rdeg[v2] = s;
    }
    __syncthreads();
    if (tid == 0) {
        int off = 0, roff = 0;
        for (int vv = 0; vv < Vc; vv++) {
            soff[vv] = off;   off  += sdeg[vv];
            rsoff[vv] = roff; roff += rdeg[vv];
        }
        soff[Vc] = off; rsoff[Vc] = roff;
    }
    __syncthreads();
    if (tid <= Vc) { d_off[tid] = soff[tid]; d_roff[tid] = rsoff[tid]; }
    {
        int p = soff[v], rp = rsoff[v];
        for (int qq = 0; qq < 16; qq++) if (qq < q) { p += cnt16[v][qq]; rp += rcnt16[v][qq]; }
        for (int e = lo; e < hi; e++) {
            if (dst[e] == v) d_srcs[p++] = src[e];
            if (src[e] == v) d_rdst[rp++] = dst[e];
        }
    }
}

// ---------------- main: NG=16, 768 thr, 1 block/SM ----------------
// smem floats:
//  xs[3072] | sW[512] sA[64] sD[64] sbias[32] | hbuf[16*1280] | est[16*544] edt[16*544]
//  invd[16*272] accs[16*68] | gsm[16*32] | ints: soff[65] ssrc[512] roff[65] rdst[512]
#define OFF_W    XS_F
#define OFF_A    (OFF_W + 512)
#define OFF_D    (OFF_A + 64)
#define OFF_BIAS (OFF_D + 64)
#define OFF_H    (OFF_BIAS + 32)
#define OFF_EST  (OFF_H + NG * HG16)
#define OFF_EDT  (OFF_EST + NG * 544)
#define OFF_INV  (OFF_EDT + NG * 544)
#define OFF_ACC  (OFF_INV + NG * 272)
#define OFF_GS   (OFF_ACC + NG * 68)
#define SM_FLOATS (OFF_GS + NG * 32)
#define MAIN_SMEM (SM_FLOATS * 4 + (2 * (Vc + 1) + 2 * EMAX) * 4)

__global__ void __launch_bounds__(NTHR, 1)
main_kernel(const float* __restrict__ x,
            const float* __restrict__ gat_w,
            const float* __restrict__ bias_g,
            int E) {
    extern __shared__ float sm[];
    float* xs    = sm;
    float* sW    = sm + OFF_W;
    float* sA    = sm + OFF_A;
    float* sD    = sm + OFF_D;
    float* sbias = sm + OFF_BIAS;
    float* hbuf  = sm + OFF_H;                 // [g][v][H16]
    float* gsm   = sm + OFF_GS;                // [g][32] projected outputs
    int*   soff  = (int*)(sm + SM_FLOATS);
    int*   ssrc  = soff + (Vc + 1);
    int*   sroff = ssrc + EMAX;
    int*   srdst = sroff + (Vc + 1);

    const int tid = threadIdx.x;
    const int bx  = blockIdx.x;
    const int b   = bx / (Tc / NG);
    const int tcb = bx % (Tc / NG);
    const int t0  = tcb * NG;

    for (int idx = tid; idx < XS_F; idx += NTHR) {
        int v = idx / XROW, j = idx - v * XROW;
        int t = t0 - 15 + j;
        float val = 0.f;
        if (j < NG + 31 && t >= 0 && t < Tc) val = x[(b * Vc + v) * Tc + t];
        xs[idx] = val;
    }
    for (int i = tid; i < 512; i += NTHR) sW[i] = gat_w[i];
    if (tid < 64)  { sA[tid] = d_A[tid]; sD[tid] = d_Dv[tid]; }
    if (tid < 32)  sbias[tid] = bias_g[tid];
    for (int i = tid; i < Vc + 1; i += NTHR) { soff[i] = d_off[i]; sroff[i] = d_roff[i]; }
    for (int i = tid; i < E; i += NTHR) { ssrc[i] = d_srcs[i]; srdst[i] = d_rdst[i]; }
    __syncthreads();

    // ---- conv: 16 channels, f = tid&15, 48 slots over (v, g-half) tasks ----
    // Each task computes 8 consecutive graphs (gh*8 .. gh*8+7) for one v row,
    // using the proven 9-accumulator FFMA2 inner loop.
    {
        const int f = tid & 15;
        const int slot = tid >> 4;          // 0..47
        float w[K1c];
        #pragma unroll
        for (int k = 0; k < K1c; k++) w[k] = d_wc[k * 16 + f];
        const float cv = d_bc[f];
        const ull cvu = pack2(cv, cv);
        #pragma unroll 1
        for (int task = slot; task < 128; task += 48) {
            const int v  = task & 63;
            const int gh = task >> 6;       // 0 or 1
            const float* xr = xs + v * XROW + gh * 8;
            ull pe[20];
            #pragma unroll
            for (int j = 0; j < 8; j++) pe[j] = *(const ull*)(xr + 2 * j);
            ull acc2[4], accO[5];
            #pragma unroll
            for (int p = 0; p < 4; p++) acc2[p] = cvu;
            #pragma unroll
            for (int q = 0; q < 5; q++) accO[q] = 0ULL;
            #pragma unroll
            for (int kh = 0; kh < 16; kh++) {
                if (kh < 12) pe[kh + 8] = *(const ull*)(xr + 2 * (kh + 8));
                const ull w0 = pack2(w[2 * kh],     w[2 * kh]);
                const ull w1 = pack2(w[2 * kh + 1], w[2 * kh + 1]);
                #pragma unroll
                for (int p = 0; p < 4; p++) fma2(acc2[p], w0, pe[kh + p]);
                #pragma unroll
                for (int q = 0; q < 5; q++) fma2(accO[q], w1, pe[kh + q]);
            }
            float elo[4], ehi[4], olo[5], ohi[5];
            #pragma unroll
            for (int p = 0; p < 4; p++) unpack2(acc2[p], elo[p], ehi[p]);
            #pragma unroll
            for (int q = 0; q < 5; q++) unpack2(accO[q], olo[q], ohi[q]);
            float* hb = hbuf + gh * 8 * HG16;
            #pragma unroll
            for (int p = 0; p < 4; p++) {
                hb[(2 * p)     * HG16 + v * H16 + f] = elo[p] + ohi[p];
                hb[(2 * p + 1) * HG16 + v * H16 + f] = ehi[p] + olo[p + 1];
            }
        }
    }
    __syncthreads();

    // ---- GAT (warps 0..15): scalar edge passes + per-source 16-dim accumulation ----
    const int warp = tid >> 5, lane = tid & 31;
    if (warp < NG) {
        float*  h    = hbuf + warp * HG16;
        float2* est  = (float2*)(sm + OFF_EST) + warp * 272;   // [head*68 + v]
        float2* edt  = (float2*)(sm + OFF_EDT) + warp * 272;
        float*  invd = sm + OFF_INV + warp * 272;              // [head*68 + d]
        float*  accs = sm + OFF_ACC + warp * 68;               // [head*17 + f]

        // pass A: es/ed dots (16-dim) + exp tables
        #pragma unroll
        for (int i = 0; i < 8; i++) {
            int p = lane + 32 * i;
            int head = p & 3, v = p >> 2;
            const float4* hv = (const float4*)(h + v * H16);
            const float4* Ap = (const float4*)(sA + head * 16);
            const float4* Dp = (const float4*)(sD + head * 16);
            float es = 0.f, ed = 0.f;
            #pragma unroll
            for (int j = 0; j < 4; j++) {
                float4 hq = hv[j], aq = Ap[j], dq = Dp[j];
                es = fmaf(hq.x, aq.x, fmaf(hq.y, aq.y, fmaf(hq.z, aq.z, fmaf(hq.w, aq.w, es))));
                ed = fmaf(hq.x, dq.x, fmaf(hq.y, dq.y, fmaf(hq.z, dq.z, fmaf(hq.w, dq.w, ed))));
            }
            est[head * 68 + v] = make_float2(__expf(es), __expf(0.2f * es));
            edt[head * 68 + v] = make_float2(__expf(ed), __expf(0.2f * ed));
        }
        __syncwarp();

        const int head = lane & 3;
        // pass B: denominators (scalar edge loop over forward CSR)
        #pragma unroll 1
        for (int i = 0; i < 8; i++) {
            const int d = (lane >> 2) + 8 * i;
            const float2 Dd = edt[head * 68 + d];
            const int beg = soff[d], end = soff[d + 1];
            float den = 0.f;
            for (int e = beg; e < end; e++) {
                float2 Es = est[head * 68 + ssrc[e]];
                float p = Es.x * Dd.x;
                den += (p > 1.f) ? p : Es.y * Dd.y;
            }
            invd[head * 68 + d] = __frcp_rn(den);
        }
        __syncwarp();

        // pass C: beta per source (reverse CSR, scalar), then 16-dim accumulate
        ull acc8[8];
        #pragma unroll
        for (int j = 0; j < 8; j++) acc8[j] = 0ULL;
        #pragma unroll 1
        for (int i = 0; i < 8; i++) {
            const int s = (lane >> 2) + 8 * i;
            const float2 Es = est[head * 68 + s];
            const int beg = sroff[s], end = sroff[s + 1];
            float beta = 0.f;
            for (int e = beg; e < end; e++) {
                int d = srdst[e];
                float2 Dd = edt[head * 68 + d];
                float p = Es.x * Dd.x;
                float wexp = (p > 1.f) ? p : Es.y * Dd.y;
                beta = fmaf(wexp, invd[head * 68 + d], beta);
            }
            const ull bp = pack2(beta, beta);
            const ull* hs = (const ull*)(h + s * H16);
            #pragma unroll
            for (int j = 0; j < 8; j++) fma2(acc8[j], bp, hs[j]);
        }
        float a16[16];
        #pragma unroll
        for (int j = 0; j < 8; j++) unpack2(acc8[j], a16[2 * j], a16[2 * j + 1]);
        #pragma unroll
        for (int o = 0; o < 16; o++) {
            a16[o] += __shfl_xor_sync(0xffffffffu, a16[o], 4);
            a16[o] += __shfl_xor_sync(0xffffffffu, a16[o], 8);
            a16[o] += __shfl_xor_sync(0xffffffffu, a16[o], 16);
        }
        if (lane < 4) {
            #pragma unroll
            for (int f2 = 0; f2 < 16; f2++) accs[lane * 17 + f2] = a16[f2];
        }
        __syncwarp();

        // final projection 16 -> 32, stash in smem for in-block pooling
        {
            const int ho = lane;
            const int hd = lane >> 3;
            float m = 0.f;
            #pragma unroll
            for (int f2 = 0; f2 < 16; f2++)
                m = fmaf(sW[f2 * 32 + ho], accs[hd * 17 + f2], m);
            gsm[warp * 32 + ho] = m * (1.0f / 64.0f) + sbias[ho];
        }
    }
    __syncthreads();

    // ---- fused BN2 + ELU + pool8: two pool windows per block ----
    if (tid < 64) {
        const int pw = tid >> 5;            // pool window 0/1
        const int fo = tid & 31;
        const float sc = d_scale2[fo], sh = d_shift2[fo];
        float s = 0.f;
        #pragma unroll
        for (int r = 0; r < 8; r++) {
            float gv = fmaf(sc, gsm[(pw * 8 + r) * 32 + fo], sh);
            s += gv > 0.f ? gv : (__expf(gv) - 1.f);
        }
        d_pbuf[(b * TP + tcb * 2 + pw) * 32 + fo] = s * 0.125f;
    }
}

// ---------------- tail: conv3 + BN3 + ELU + pool4 (pooled input precomputed) ----------------
#define TAIL_SMEM ((F2c * F2c * K3c + F2c * 40 + F2c * 24) * 4)

__global__ void __launch_bounds__(256)
tail_kernel(const float* __restrict__ conv3_w, float* __restrict__ out) {
    extern __shared__ float sm[];
    float* w3s   = sm;
    float* ptile = w3s + F2c * F2c * K3c;
    float* ytile = ptile + F2c * 40;

    const int tid = threadIdx.x;
    const int b = blockIdx.x;
    const int tile = blockIdx.y;
    const int tc0 = tile * 24;

    for (int i = tid; i < F2c * F2c * K3c; i += 256) w3s[i] = conv3_w[i];
    for (int i = tid; i < F2c * 40; i += 256) {
        int fi = i & 31, j = i >> 5;
        int tc = tc0 - 7 + j;
        float val = 0.f;
        if (j < 39 && tc >= 0 && tc < TP) val = d_pbuf[(b * TP + tc) * 32 + fi];
        ptile[fi * 40 + j] = val;
    }
    __syncthreads();

    for (int oidx = tid; oidx < F2c * 24; oidx += 256) {
        int fo = oidx / 24;
        int tcl = oidx - fo * 24;
        float acc = 0.f;
        for (int fi = 0; fi < F2c; fi++) {
            const float* wr = w3s + (fo * 32 + fi) * 16;
            const float* pr = ptile + fi * 40 + tcl;
            #pragma unroll
            for (int k = 0; k < K3c; k++) acc = fmaf(wr[k], pr[k], acc);
        }
        float z = fmaf(d_scale3[fo], acc, d_shift3[fo]);
        z = z > 0.f ? z : (__expf(z) - 1.f);
        ytile[fo * 24 + tcl] = z;
    }
    __syncthreads();

    for (int i = tid; i < F2c * 6; i += 256) {
        int fo = i / 6, tl = i - fo * 6;
        const float* yr = ytile + fo * 24 + tl * 4;
        float s = 0.25f * (yr[0] + yr[1] + yr[2] + yr[3]);
        out[(b * 32 + fo) * 48 + tile * 6 + tl] = s;
    }
}

// ---------------- launch ----------------
extern "C" void kernel_launch(void* const* d_in, const int* in_sizes, int n_in,
                              void* d_out, int out_size) {
    const float* x        = (const float*)d_in[0];
    const float* conv1_w  = (const float*)d_in[1];
    const float* bn1_g    = (const float*)d_in[2];
    const float* bn1_b    = (const float*)d_in[3];
    const float* bn1_m    = (const float*)d_in[4];
    const float* bn1_v    = (const float*)d_in[5];
    const float* gat_w    = (const float*)d_in[6];
    const float* gat_asrc = (const float*)d_in[7];
    const float* gat_adst = (const float*)d_in[8];
    const float* gat_bias = (const float*)d_in[9];
    const float* bn2_g    = (const float*)d_in[10];
    const float* bn2_b    = (const float*)d_in[11];
    const float* bn2_m    = (const float*)d_in[12];
    const float* bn2_v    = (const float*)d_in[13];
    const float* conv3_w  = (const float*)d_in[14];
    const float* bn3_g    = (const float*)d_in[15];
    const float* bn3_b    = (const float*)d_in[16];
    const float* bn3_m    = (const float*)d_in[17];
    const float* bn3_v    = (const float*)d_in[18];
    const int*   edge_idx = (const int*)d_in[19];
    int E = in_sizes[19] / 2;
    if (E > EMAX) E = EMAX;

    cudaFuncSetAttribute(main_kernel, cudaFuncAttributeMaxDynamicSharedMemorySize, MAIN_SMEM);
    cudaFuncSetAttribute(tail_kernel, cudaFuncAttributeMaxDynamicSharedMemorySize, TAIL_SMEM);

    setup_kernel<<<1, 1024>>>(conv1_w, bn1_g, bn1_b, bn1_m, bn1_v, gat_w,
                              gat_asrc, gat_adst,
                              bn2_g, bn2_b, bn2_m, bn2_v,
                              bn3_g, bn3_b, bn3_m, bn3_v, edge_idx, E);
    main_kernel<<<Bc * (Tc / NG), NTHR, MAIN_SMEM>>>(x, gat_w, gat_bias, E);
    tail_kernel<<<dim3(Bc, 8), 256, TAIL_SMEM>>>(conv3_w, (float*)d_out);
}

// round 17
// speedup vs baseline: 1.0562x; 1.0562x over previous
#include <cuda_runtime.h>
#include <math.h>

// ---------------- problem constants ----------------
#define Bc   16
#define Tc   1536
#define Vc   64
#define F1c  16
#define Hc   4
#define FOc  8
#define F2c  32
#define K1c  32
#define K3c  16
#define NG   8
#define EMAX 512
#define NTHR 384
#define TP   192

#define XROW 40
#define XS_F (Vc * XROW)
// h1 (16-ch) row stride
#define H16  20
#define HG16 (Vc * H16)     // 1280 floats per graph

// ---------------- device scratch ----------------
__device__ float d_wc[K1c * 16];   // [k][f]  bn-folded conv weights
__device__ float d_bc[16];         // bn shift per f
__device__ float d_A[64];          // [head][16]  W·a_src folded
__device__ float d_Dv[64];         // [head][16]  W·a_dst folded
__device__ float d_scale2[32], d_shift2[32], d_scale3[32], d_shift3[32];
__device__ int   d_off[Vc + 1];
__device__ int   d_srcs[EMAX];
__device__ int   d_roff[Vc + 1];
__device__ int   d_rdst[EMAX];
__device__ float d_pbuf[Bc * TP * F2c];   // pooled BN2+ELU output, (b,tc,f)

// ---------------- packed f32x2 helpers ----------------
typedef unsigned long long ull;
__device__ __forceinline__ ull pack2(float lo, float hi) {
    ull r;
    asm("mov.b64 %0, {%1, %2};" : "=l"(r) : "f"(lo), "f"(hi));
    return r;
}
__device__ __forceinline__ void fma2(ull& d, ull a, ull b) {
    asm("fma.rn.f32x2 %0, %1, %2, %0;" : "+l"(d) : "l"(a), "l"(b));
}
__device__ __forceinline__ void unpack2(ull v, float& lo, float& hi) {
    asm("mov.b64 {%0, %1}, %2;" : "=f"(lo), "=f"(hi) : "l"(v));
}
// LDS.128 producing two packed ull directly (no repack movs)
__device__ __forceinline__ void lds2u64(ull& a, ull& b, unsigned addr) {
    asm volatile("ld.shared.v2.u64 {%0, %1}, [%2];" : "=l"(a), "=l"(b) : "r"(addr));
}

// ---------------- setup: 1024 threads, parallel degree sums ----------------
__global__ void setup_kernel(const float* __restrict__ conv1_w,
                             const float* __restrict__ bn1_g, const float* __restrict__ bn1_b,
                             const float* __restrict__ bn1_m, const float* __restrict__ bn1_v,
                             const float* __restrict__ gat_w,
                             const float* __restrict__ gat_asrc, const float* __restrict__ gat_adst,
                             const float* __restrict__ bn2_g, const float* __restrict__ bn2_b,
                             const float* __restrict__ bn2_m, const float* __restrict__ bn2_v,
                             const float* __restrict__ bn3_g, const float* __restrict__ bn3_b,
                             const float* __restrict__ bn3_m, const float* __restrict__ bn3_v,
                             const int* __restrict__ edge_index, int E) {
    __shared__ float sc1[F1c], sh1[F1c];
    __shared__ float s_gw[F1c * 32];
    __shared__ int sedge[2 * EMAX];
    __shared__ int cnt16[Vc][16], rcnt16[Vc][16];
    __shared__ int sdeg[Vc], rdeg[Vc];
    __shared__ int soff[Vc + 1], rsoff[Vc + 1];
    int tid = threadIdx.x;

    for (int i = tid; i < 2 * E; i += blockDim.x) sedge[i] = edge_index[i];
    for (int i = tid; i < F1c * 32; i += blockDim.x) s_gw[i] = gat_w[i];
    if (tid < F1c) {
        float s = bn1_g[tid] * rsqrtf(bn1_v[tid] + 1e-5f);
        sc1[tid] = s;
        sh1[tid] = bn1_b[tid] - bn1_m[tid] * s;
    }
    if (tid < F2c) {
        float s2 = bn2_g[tid] * rsqrtf(bn2_v[tid] + 1e-5f);
        d_scale2[tid] = s2; d_shift2[tid] = bn2_b[tid] - bn2_m[tid] * s2;
        float s3 = bn3_g[tid] * rsqrtf(bn3_v[tid] + 1e-5f);
        d_scale3[tid] = s3; d_shift3[tid] = bn3_b[tid] - bn3_m[tid] * s3;
    }
    __syncthreads();
    for (int i = tid; i < K1c * 16; i += blockDim.x) {
        int k = i >> 4, f = i & 15;
        d_wc[i] = sc1[f] * conv1_w[f * K1c + k];
    }
    if (tid < 16) d_bc[tid] = sh1[tid];
    if (tid < 64) {
        int head = tid >> 4, f = tid & 15;
        float sa = 0.f, sd = 0.f;
        #pragma unroll
        for (int fo = 0; fo < FOc; fo++) {
            float wv = s_gw[f * 32 + head * FOc + fo];
            sa = fmaf(wv, gat_asrc[head * FOc + fo], sa);
            sd = fmaf(wv, gat_adst[head * FOc + fo], sd);
        }
        d_A[head * 16 + f]  = sa;
        d_Dv[head * 16 + f] = sd;
    }
    // forward + reverse CSR (order-preserving, 16 threads/vertex)
    const int* src = sedge;
    const int* dst = sedge + E;
    const int qsz = (E + 15) >> 4;
    const int v = tid >> 4, q = tid & 15;
    const int lo = q * qsz;
    const int hi = min(E, lo + qsz);
    {
        int c = 0, rc = 0;
        for (int e = lo; e < hi; e++) { c += (dst[e] == v); rc += (src[e] == v); }
        cnt16[v][q] = c; rcnt16[v][q] = rc;
    }
    __syncthreads();
    if (tid < Vc) {
        int s = 0;
        #pragma unroll
        for (int qq = 0; qq < 16; qq++) s += cnt16[tid][qq];
        sdeg[tid] = s;
    } else if (tid < 2 * Vc) {
        int v2 = tid - Vc;
        int s = 0;
        #pragma unroll
        for (int qq = 0; qq < 16; qq++) s += rcnt16[v2][qq];
        rdeg[v2] = s;
    }
    __syncthreads();
    if (tid == 0) {
        int off = 0, roff = 0;
        for (int vv = 0; vv < Vc; vv++) {
            soff[vv] = off;   off  += sdeg[vv];
            rsoff[vv] = roff; roff += rdeg[vv];
        }
        soff[Vc] = off; rsoff[Vc] = roff;
    }
    __syncthreads();
    if (tid <= Vc) { d_off[tid] = soff[tid]; d_roff[tid] = rsoff[tid]; }
    {
        int p = soff[v], rp = rsoff[v];
        for (int qq = 0; qq < 16; qq++) if (qq < q) { p += cnt16[v][qq]; rp += rcnt16[v][qq]; }
        for (int e = lo; e < hi; e++) {
            if (dst[e] == v) d_srcs[p++] = src[e];
            if (src[e] == v) d_rdst[rp++] = dst[e];
        }
    }
}

// ---------------- main: R15 engine + LDS.128 conv loads + GAT index prefetch ----------------
#define OFF_W    XS_F
#define OFF_A    (OFF_W + 512)
#define OFF_D    (OFF_A + 64)
#define OFF_BIAS (OFF_D + 64)
#define OFF_H    (OFF_BIAS + 32)
#define OFF_EST  (OFF_H + NG * HG16)
#define OFF_EDT  (OFF_EST + NG * 544)
#define OFF_INV  (OFF_EDT + NG * 544)
#define OFF_ACC  (OFF_INV + NG * 272)
#define OFF_GS   (OFF_ACC + NG * 68)
#define SM_FLOATS (OFF_GS + NG * 32)
#define MAIN_SMEM (SM_FLOATS * 4 + (2 * (Vc + 1) + 2 * EMAX) * 4)

__global__ void __launch_bounds__(NTHR, 2)
main_kernel(const float* __restrict__ x,
            const float* __restrict__ gat_w,
            const float* __restrict__ bias_g,
            int E) {
    extern __shared__ float sm[];
    float* xs    = sm;
    float* sW    = sm + OFF_W;
    float* sA    = sm + OFF_A;
    float* sD    = sm + OFF_D;
    float* sbias = sm + OFF_BIAS;
    float* hbuf  = sm + OFF_H;                 // [g][v][H16]
    float* gsm   = sm + OFF_GS;                // [g][32] projected outputs
    int*   soff  = (int*)(sm + SM_FLOATS);
    int*   ssrc  = soff + (Vc + 1);
    int*   sroff = ssrc + EMAX;
    int*   srdst = sroff + (Vc + 1);

    const int tid = threadIdx.x;
    const int bx  = blockIdx.x;
    const int b   = bx / (Tc / NG);
    const int tc  = bx % (Tc / NG);
    const int t0  = tc * NG;

    for (int idx = tid; idx < XS_F; idx += NTHR) {
        int v = idx / XROW, j = idx - v * XROW;
        int t = t0 - 15 + j;
        float val = 0.f;
        if (j < NG + 31 && t >= 0 && t < Tc) val = x[(b * Vc + v) * Tc + t];
        xs[idx] = val;
    }
    for (int i = tid; i < 512; i += NTHR) sW[i] = gat_w[i];
    if (tid < 64)  { sA[tid] = d_A[tid]; sD[tid] = d_Dv[tid]; }
    if (tid < 32)  sbias[tid] = bias_g[tid];
    for (int i = tid; i < Vc + 1; i += NTHR) { soff[i] = d_off[i]; sroff[i] = d_roff[i]; }
    for (int i = tid; i < E; i += NTHR) { ssrc[i] = d_srcs[i]; srdst[i] = d_rdst[i]; }
    __syncthreads();

    // ---- conv: 16 channels, f = tid&15, 24 slots over v; x via LDS.128 ----
    {
        const int f = tid & 15;
        const int slot = tid >> 4;          // 0..23
        float w[K1c];
        #pragma unroll
        for (int k = 0; k < K1c; k++) w[k] = d_wc[k * 16 + f];
        const float cv = d_bc[f];
        const ull cvu = pack2(cv, cv);
        #pragma unroll 1
        for (int v = slot; v < 64; v += 24) {
            unsigned xaddr = (unsigned)__cvta_generic_to_shared(xs + v * XROW);
            ull pe[20];
            lds2u64(pe[0], pe[1], xaddr);
            lds2u64(pe[2], pe[3], xaddr + 16);
            lds2u64(pe[4], pe[5], xaddr + 32);
            lds2u64(pe[6], pe[7], xaddr + 48);
            ull acc2[4], accO[5];
            #pragma unroll
            for (int p = 0; p < 4; p++) acc2[p] = cvu;
            #pragma unroll
            for (int q = 0; q < 5; q++) accO[q] = 0ULL;
            #pragma unroll
            for (int kh = 0; kh < 16; kh++) {
                if (kh < 12 && (kh & 1) == 0)
                    lds2u64(pe[kh + 8], pe[kh + 9], xaddr + 64 + kh * 8);
                const ull w0 = pack2(w[2 * kh],     w[2 * kh]);
                const ull w1 = pack2(w[2 * kh + 1], w[2 * kh + 1]);
                #pragma unroll
                for (int p = 0; p < 4; p++) fma2(acc2[p], w0, pe[kh + p]);
                #pragma unroll
                for (int q = 0; q < 5; q++) fma2(accO[q], w1, pe[kh + q]);
            }
            float elo[4], ehi[4], olo[5], ohi[5];
            #pragma unroll
            for (int p = 0; p < 4; p++) unpack2(acc2[p], elo[p], ehi[p]);
            #pragma unroll
            for (int q = 0; q < 5; q++) unpack2(accO[q], olo[q], ohi[q]);
            #pragma unroll
            for (int p = 0; p < 4; p++) {
                hbuf[(2 * p)     * HG16 + v * H16 + f] = elo[p] + ohi[p];
                hbuf[(2 * p + 1) * HG16 + v * H16 + f] = ehi[p] + olo[p + 1];
            }
        }
    }
    __syncthreads();

    // ---- GAT (warps 0..7): scalar edge passes with index prefetch ----
    const int warp = tid >> 5, lane = tid & 31;
    if (warp < NG) {
        float*  h    = hbuf + warp * HG16;
        float2* est  = (float2*)(sm + OFF_EST) + warp * 272;   // [head*68 + v]
        float2* edt  = (float2*)(sm + OFF_EDT) + warp * 272;
        float*  invd = sm + OFF_INV + warp * 272;              // [head*68 + d]
        float*  accs = sm + OFF_ACC + warp * 68;               // [head*17 + f]

        // pass A: es/ed dots (16-dim) + exp tables
        #pragma unroll
        for (int i = 0; i < 8; i++) {
            int p = lane + 32 * i;
            int head = p & 3, v = p >> 2;
            const float4* hv = (const float4*)(h + v * H16);
            const float4* Ap = (const float4*)(sA + head * 16);
            const float4* Dp = (const float4*)(sD + head * 16);
            float es = 0.f, ed = 0.f;
            #pragma unroll
            for (int j = 0; j < 4; j++) {
                float4 hq = hv[j], aq = Ap[j], dq = Dp[j];
                es = fmaf(hq.x, aq.x, fmaf(hq.y, aq.y, fmaf(hq.z, aq.z, fmaf(hq.w, aq.w, es))));
                ed = fmaf(hq.x, dq.x, fmaf(hq.y, dq.y, fmaf(hq.z, dq.z, fmaf(hq.w, dq.w, ed))));
            }
            est[head * 68 + v] = make_float2(__expf(es), __expf(0.2f * es));
            edt[head * 68 + v] = make_float2(__expf(ed), __expf(0.2f * ed));
        }
        __syncwarp();

        const int head = lane & 3;
        // pass B: denominators (forward CSR, index prefetch; deg>=1 via self-loops)
        #pragma unroll 1
        for (int i = 0; i < 8; i++) {
            const int d = (lane >> 2) + 8 * i;
            const float2 Dd = edt[head * 68 + d];
            const int beg = soff[d], end = soff[d + 1];
            float den = 0.f;
            int scur = ssrc[beg];
            #pragma unroll 1
            for (int e = beg; e < end; e++) {
                int snxt = (e + 1 < end) ? ssrc[e + 1] : scur;
                float2 Es = est[head * 68 + scur];
                float p = Es.x * Dd.x;
                den += (p > 1.f) ? p : Es.y * Dd.y;
                scur = snxt;
            }
            invd[head * 68 + d] = __frcp_rn(den);
        }
        __syncwarp();

        // pass C: beta per source (reverse CSR, index prefetch), then 16-dim accumulate
        ull acc8[8];
        #pragma unroll
        for (int j = 0; j < 8; j++) acc8[j] = 0ULL;
        #pragma unroll 1
        for (int i = 0; i < 8; i++) {
            const int s = (lane >> 2) + 8 * i;
            const float2 Es = est[head * 68 + s];
            const int beg = sroff[s], end = sroff[s + 1];
            float beta = 0.f;
            int dcur = srdst[beg];
            #pragma unroll 1
            for (int e = beg; e < end; e++) {
                int dnxt = (e + 1 < end) ? srdst[e + 1] : dcur;
                float2 Dd = edt[head * 68 + dcur];
                float iv  = invd[head * 68 + dcur];
                float p = Es.x * Dd.x;
                float wexp = (p > 1.f) ? p : Es.y * Dd.y;
                beta = fmaf(wexp, iv, beta);
                dcur = dnxt;
            }
            const ull bp = pack2(beta, beta);
            const ull* hs = (const ull*)(h + s * H16);
            #pragma unroll
            for (int j = 0; j < 8; j++) fma2(acc8[j], bp, hs[j]);
        }
        float a16[16];
        #pragma unroll
        for (int j = 0; j < 8; j++) unpack2(acc8[j], a16[2 * j], a16[2 * j + 1]);
        #pragma unroll
        for (int o = 0; o < 16; o++) {
            a16[o] += __shfl_xor_sync(0xffffffffu, a16[o], 4);
            a16[o] += __shfl_xor_sync(0xffffffffu, a16[o], 8);
            a16[o] += __shfl_xor_sync(0xffffffffu, a16[o], 16);
        }
        if (lane < 4) {
            #pragma unroll
            for (int f2 = 0; f2 < 16; f2++) accs[lane * 17 + f2] = a16[f2];
        }
        __syncwarp();

        // final projection 16 -> 32, stash in smem for in-block pooling
        {
            const int ho = lane;
            const int hd = lane >> 3;
            float m = 0.f;
            #pragma unroll
            for (int f2 = 0; f2 < 16; f2++)
                m = fmaf(sW[f2 * 32 + ho], accs[hd * 17 + f2], m);
            gsm[warp * 32 + ho] = m * (1.0f / 64.0f) + sbias[ho];
        }
    }
    __syncthreads();

    // ---- fused BN2 + ELU + pool8 over this block's 8 t-values ----
    if (tid < 32) {
        const float sc = d_scale2[tid], sh = d_shift2[tid];
        float s = 0.f;
        #pragma unroll
        for (int r = 0; r < 8; r++) {
            float gv = fmaf(sc, gsm[r * 32 + tid], sh);
            s += gv > 0.f ? gv : (__expf(gv) - 1.f);
        }
        d_pbuf[(b * TP + tc) * 32 + tid] = s * 0.125f;
    }
}

// ---------------- tail: conv3 + BN3 + ELU + pool4 (pooled input precomputed) ----------------
#define TAIL_SMEM ((F2c * F2c * K3c + F2c * 40 + F2c * 24) * 4)

__global__ void __launch_bounds__(256)
tail_kernel(const float* __restrict__ conv3_w, float* __restrict__ out) {
    extern __shared__ float sm[];
    float* w3s   = sm;
    float* ptile = w3s + F2c * F2c * K3c;
    float* ytile = ptile + F2c * 40;

    const int tid = threadIdx.x;
    const int b = blockIdx.x;
    const int tile = blockIdx.y;
    const int tc0 = tile * 24;

    for (int i = tid; i < F2c * F2c * K3c; i += 256) w3s[i] = conv3_w[i];
    for (int i = tid; i < F2c * 40; i += 256) {
        int fi = i & 31, j = i >> 5;
        int tc = tc0 - 7 + j;
        float val = 0.f;
        if (j < 39 && tc >= 0 && tc < TP) val = d_pbuf[(b * TP + tc) * 32 + fi];
        ptile[fi * 40 + j] = val;
    }
    __syncthreads();

    for (int oidx = tid; oidx < F2c * 24; oidx += 256) {
        int fo = oidx / 24;
        int tcl = oidx - fo * 24;
        float acc = 0.f;
        for (int fi = 0; fi < F2c; fi++) {
            const float* wr = w3s + (fo * 32 + fi) * 16;
            const float* pr = ptile + fi * 40 + tcl;
            #pragma unroll
            for (int k = 0; k < K3c; k++) acc = fmaf(wr[k], pr[k], acc);
        }
        float z = fmaf(d_scale3[fo], acc, d_shift3[fo]);
        z = z > 0.f ? z : (__expf(z) - 1.f);
        ytile[fo * 24 + tcl] = z;
    }
    __syncthreads();

    for (int i = tid; i < F2c * 6; i += 256) {
        int fo = i / 6, tl = i - fo * 6;
        const float* yr = ytile + fo * 24 + tl * 4;
        float s = 0.25f * (yr[0] + yr[1] + yr[2] + yr[3]);
        out[(b * 32 + fo) * 48 + tile * 6 + tl] = s;
    }
}

// ---------------- launch ----------------
extern "C" void kernel_launch(void* const* d_in, const int* in_sizes, int n_in,
                              void* d_out, int out_size) {
    const float* x        = (const float*)d_in[0];
    const float* conv1_w  = (const float*)d_in[1];
    const float* bn1_g    = (const float*)d_in[2];
    const float* bn1_b    = (const float*)d_in[3];
    const float* bn1_m    = (const float*)d_in[4];
    const float* bn1_v    = (const float*)d_in[5];
    const float* gat_w    = (const float*)d_in[6];
    const float* gat_asrc = (const float*)d_in[7];
    const float* gat_adst = (const float*)d_in[8];
    const float* gat_bias = (const float*)d_in[9];
    const float* bn2_g    = (const float*)d_in[10];
    const float* bn2_b    = (const float*)d_in[11];
    const float* bn2_m    = (const float*)d_in[12];
    const float* bn2_v    = (const float*)d_in[13];
    const float* conv3_w  = (const float*)d_in[14];
    const float* bn3_g    = (const float*)d_in[15];
    const float* bn3_b    = (const float*)d_in[16];
    const float* bn3_m    = (const float*)d_in[17];
    const float* bn3_v    = (const float*)d_in[18];
    const int*   edge_idx = (const int*)d_in[19];
    int E = in_sizes[19] / 2;
    if (E > EMAX) E = EMAX;

    cudaFuncSetAttribute(main_kernel, cudaFuncAttributeMaxDynamicSharedMemorySize, MAIN_SMEM);
    cudaFuncSetAttribute(tail_kernel, cudaFuncAttributeMaxDynamicSharedMemorySize, TAIL_SMEM);

    setup_kernel<<<1, 1024>>>(conv1_w, bn1_g, bn1_b, bn1_m, bn1_v, gat_w,
                              gat_asrc, gat_adst,
                              bn2_g, bn2_b, bn2_m, bn2_v,
                              bn3_g, bn3_b, bn3_m, bn3_v, edge_idx, E);
    main_kernel<<<Bc * (Tc / NG), NTHR, MAIN_SMEM>>>(x, gat_w, gat_bias, E);
    tail_kernel<<<dim3(Bc, 8), 256, TAIL_SMEM>>>(conv3_w, (float*)d_out);
}